// round 9
// baseline (speedup 1.0000x reference)
#include <cuda_runtime.h>

#define NTOT 16384   // B*N
#define NPTS 8192    // N per batch
#define KNN  16
#define DOUT 128
#define NLANES (8 * NTOT)    // scan lanes (8 per query)
#define CAP 120              // log capacity per lane
#define SPN 256              // sample pairs per batch (=512 keys)

// ---- scratch (__device__ globals: allocation-free) ----
__device__ float4 g_keysA[NTOT / 2];     // (x0,x1,y0,y1) per key pair
__device__ float4 g_keysB[NTOT / 2];     // (z0,z1,n0,n1) per key pair
__device__ float  g_Q[NTOT * DOUT];
__device__ float  g_P[NTOT * DOUT];
__device__ float  g_T0[NTOT];            // per-query distance upper bound
__device__ float  g_logd[CAP * NLANES];  // candidate distances
__device__ int    g_logi[CAP * NLANES];  // candidate ids (batch-local)
__device__ int    g_cnt[NLANES];
__device__ int    g_id[NTOT * KNN];
__device__ float  g_w[NTOT * KNN];

// ---- f32x2 packed helpers (two independent IEEE-rn fp32 ops) ----
__device__ __forceinline__ unsigned long long pk2(float lo, float hi) {
    unsigned long long v;
    asm("mov.b64 %0, {%1, %2};" : "=l"(v) : "f"(lo), "f"(hi));
    return v;
}
__device__ __forceinline__ void unpk2(float& lo, float& hi, unsigned long long v) {
    asm("mov.b64 {%0, %1}, %2;" : "=f"(lo), "=f"(hi) : "l"(v));
}
__device__ __forceinline__ unsigned long long mul2(unsigned long long a, unsigned long long b) {
    unsigned long long d;
    asm("mul.rn.f32x2 %0, %1, %2;" : "=l"(d) : "l"(a), "l"(b));
    return d;
}
__device__ __forceinline__ unsigned long long add2(unsigned long long a, unsigned long long b) {
    unsigned long long d;
    asm("add.rn.f32x2 %0, %1, %2;" : "=l"(d) : "l"(a), "l"(b));
    return d;
}
__device__ __forceinline__ unsigned long long fma2_(unsigned long long a, unsigned long long b,
                                                    unsigned long long c) {
    unsigned long long d;
    asm("fma.rn.f32x2 %0, %1, %2, %3;" : "=l"(d) : "l"(a), "l"(b), "l"(c));
    return d;
}

// packed distance for one key pair: d2 = (qn+kn) - 2*dot, reference rounding
__device__ __forceinline__ void dist2(float4 A, float4 Bv,
                                      unsigned long long qx2, unsigned long long qy2,
                                      unsigned long long qz2, unsigned long long qn2,
                                      unsigned long long m22, float& s0, float& s1) {
    unsigned long long kx2 = *(const unsigned long long*)&A.x;
    unsigned long long ky2 = *(const unsigned long long*)&A.z;
    unsigned long long kz2 = *(const unsigned long long*)&Bv.x;
    unsigned long long kn2 = *(const unsigned long long*)&Bv.z;
    unsigned long long dt = add2(add2(mul2(qx2, kx2), mul2(qy2, ky2)), mul2(qz2, kz2));
    unsigned long long d2 = fma2_(dt, m22, add2(qn2, kn2));   // -2*dot exact
    unpk2(s0, s1, d2);
}

// carry-insert one (d,id) into sorted ascending 16-list, strict <
__device__ __forceinline__ void ins16(float (&d)[KNN], int (&id)[KNN], float cv, int ci) {
#pragma unroll
    for (int t = 0; t < KNN; t++) {
        bool p = cv < d[t];
        float od = d[t]; int oi = id[t];
        d[t]  = p ? cv : od;
        id[t] = p ? ci : oi;
        cv    = p ? od : cv;
        ci    = p ? oi : ci;
    }
}

// ============================================================
// 1) pack keys in pairs: A=(x0,x1,y0,y1), B=(z0,z1,n0,n1)
// ============================================================
__global__ void pack_kernel(const float* __restrict__ xyz1) {
    int p = blockIdx.x * 256 + threadIdx.x;
    if (p >= NTOT / 2) return;
    int k0 = 2 * p;
    float x0 = xyz1[3 * k0 + 0], y0 = xyz1[3 * k0 + 1], z0 = xyz1[3 * k0 + 2];
    float x1 = xyz1[3 * k0 + 3], y1 = xyz1[3 * k0 + 4], z1 = xyz1[3 * k0 + 5];
    float n0 = __fadd_rn(__fadd_rn(__fmul_rn(x0, x0), __fmul_rn(y0, y0)), __fmul_rn(z0, z0));
    float n1 = __fadd_rn(__fadd_rn(__fmul_rn(x1, x1), __fmul_rn(y1, y1)), __fmul_rn(z1, z1));
    g_keysA[p] = make_float4(x0, x1, y0, y1);
    g_keysB[p] = make_float4(z0, z1, n0, n1);
}

// ============================================================
// 2a) sample kernel: exact 16th-smallest distance over a fixed
//     512-key subsample (pairs stride 16) -> upper bound T0[q].
//     Values only; fmin/fmax carry chain; smem value-stack.
// ============================================================
__global__ void __launch_bounds__(256) sample_kernel(const float* __restrict__ xyz2) {
    __shared__ float4 sA[SPN], sB[SPN];
    __shared__ float stk[16 * 256];
    int tid = threadIdx.x;
    int q = blockIdx.x * 256 + tid;
    int b = q >> 13;                         // uniform per block
    sA[tid] = g_keysA[b * 4096 + tid * 16];
    sB[tid] = g_keysB[b * 4096 + tid * 16];
    __syncthreads();

    float qx = xyz2[3 * q + 0], qy = xyz2[3 * q + 1], qz = xyz2[3 * q + 2];
    float qn = __fadd_rn(__fadd_rn(__fmul_rn(qx, qx), __fmul_rn(qy, qy)), __fmul_rn(qz, qz));
    unsigned long long qx2 = pk2(qx, qx), qy2 = pk2(qy, qy), qz2 = pk2(qz, qz);
    unsigned long long qn2 = pk2(qn, qn), m22 = pk2(-2.0f, -2.0f);
    const float FINF = __int_as_float(0x7f800000);

    float d[KNN];
#pragma unroll
    for (int j = 0; j < KNN; j++) d[j] = 3.0e38f;
    int cnt = 0;

    for (int pp = 0; pp < SPN; pp += 4) {
        if (__any_sync(0xffffffffu, cnt >= 8)) {
            for (int j = 0; j < 16; j++) {
                if (!__any_sync(0xffffffffu, j < cnt)) break;
                float cv = (j < cnt) ? stk[j * 256 + tid] : FINF;
#pragma unroll
                for (int t = 0; t < KNN; t++) {
                    float lo = fminf(cv, d[t]);
                    cv = fmaxf(cv, d[t]);
                    d[t] = lo;
                }
            }
            cnt = 0;
        }
#pragma unroll
        for (int u = 0; u < 4; u++) {
            float s0, s1;
            dist2(sA[pp + u], sB[pp + u], qx2, qy2, qz2, qn2, m22, s0, s1);
            if (s0 < d[KNN - 1]) { stk[min(cnt, 15) * 256 + tid] = s0; cnt++; }
            if (s1 < d[KNN - 1]) { stk[min(cnt, 15) * 256 + tid] = s1; cnt++; }
        }
    }
    for (int j = 0; j < 16; j++) {
        if (!__any_sync(0xffffffffu, j < cnt)) break;
        float cv = (j < cnt) ? stk[j * 256 + tid] : FINF;
#pragma unroll
        for (int t = 0; t < KNN; t++) {
            float lo = fminf(cv, d[t]);
            cv = fmaxf(cv, d[t]);
            d[t] = lo;
        }
    }
    g_T0[q] = d[KNN - 1];
}

// ============================================================
// 2b) main scan: pure streaming, no maintenance. 256 blocks x
//     512 threads, 8 lanes/query. Push (d,id) with d <= T0[q]
//     to the global log (expected ~32/lane, cap 120).
// ============================================================
__global__ void __launch_bounds__(512, 2) scan_kernel(const float* __restrict__ xyz2) {
    extern __shared__ char smraw[];
    float4* skA = (float4*)smraw;                // 2048 pairs, 32KB
    float4* skB = (float4*)(smraw + 32768);      // 32KB

    int tid  = threadIdx.x;
    int ql   = tid & 127;
    int h    = tid >> 7;
    int qg   = blockIdx.x >> 1;
    int half = blockIdx.x & 1;
    int q    = qg * 128 + ql;
    int b    = q >> 13;

    const float4* gA = g_keysA + b * 4096 + half * 2048;
    const float4* gB = g_keysB + b * 4096 + half * 2048;
    for (int i = tid; i < 2048; i += 512) { skA[i] = gA[i]; skB[i] = gB[i]; }
    __syncthreads();

    float T0 = g_T0[q];
    float qx = xyz2[3 * q + 0], qy = xyz2[3 * q + 1], qz = xyz2[3 * q + 2];
    float qn = __fadd_rn(__fadd_rn(__fmul_rn(qx, qx), __fmul_rn(qy, qy)), __fmul_rn(qz, qz));
    unsigned long long qx2 = pk2(qx, qx), qy2 = pk2(qy, qy), qz2 = pk2(qz, qz);
    unsigned long long qn2 = pk2(qn, qn), m22 = pk2(-2.0f, -2.0f);

    int lane = (half * 4 + h) * NTOT + q;
    int cnt = 0;
    int pb = h * 512;
    int kb = half * 4096 + h * 1024;

#pragma unroll 4
    for (int pp = 0; pp < 512; pp++) {
        float s0, s1;
        dist2(skA[pb + pp], skB[pb + pp], qx2, qy2, qz2, qn2, m22, s0, s1);
        int k = kb + 2 * pp;
        if (s0 <= T0) {
            int e = min(cnt, CAP - 1);
            g_logd[e * NLANES + lane] = s0;
            g_logi[e * NLANES + lane] = k;
            cnt++;
        }
        if (s1 <= T0) {
            int e = min(cnt, CAP - 1);
            g_logd[e * NLANES + lane] = s1;
            g_logi[e * NLANES + lane] = k + 1;
            cnt++;
        }
    }
    g_cnt[lane] = min(cnt, CAP);
}

// ============================================================
// 2c) final select: per query, exact 16th T from logged values,
//     then collect entries <= T (id-ascending order across lanes
//     => exact top_k tie semantics), sort via carry-insert,
//     compute inverse-distance weights.
// ============================================================
__global__ void __launch_bounds__(256) final_kernel() {
    __shared__ float2 sc[24 * 256];   // 48KB
    int tid = threadIdx.x;
    int q = blockIdx.x * 256 + tid;

    float d[KNN];
#pragma unroll
    for (int j = 0; j < KNN; j++) d[j] = 3.0e38f;
    int cs[8];

    // pass 1: values only -> exact 16th
#pragma unroll
    for (int l = 0; l < 8; l++) {
        int lane = l * NTOT + q;
        int c = g_cnt[lane];
        cs[l] = c;
        for (int e = 0; e < c; e++) {
            float v = g_logd[e * NLANES + lane];
            if (v < d[KNN - 1]) {
                float cv = v;
#pragma unroll
                for (int t = 0; t < KNN; t++) {
                    float lo = fminf(cv, d[t]);
                    cv = fmaxf(cv, d[t]);
                    d[t] = lo;
                }
            }
        }
    }
    float T = d[KNN - 1];

    // pass 2: collect entries <= T, in ascending-id order
    int cnt = 0;
#pragma unroll
    for (int l = 0; l < 8; l++) {
        int lane = l * NTOT + q;
        int c = cs[l];
        for (int e = 0; e < c; e++) {
            float v = g_logd[e * NLANES + lane];
            if (v <= T) {
                int s = min(cnt, 23);
                sc[s * 256 + tid] = make_float2(v, __int_as_float(g_logi[e * NLANES + lane]));
                cnt++;
            }
        }
    }
    int m = min(cnt, 24);

    float dd[KNN]; int id[KNN];
#pragma unroll
    for (int j = 0; j < KNN; j++) { dd[j] = 3.0e38f; id[j] = 0; }
    for (int j = 0; j < m; j++) {
        float2 v = sc[j * 256 + tid];
        ins16(dd, id, v.x, __float_as_int(v.y));
    }

    float r[KNN]; float sum = 0.f;
#pragma unroll
    for (int j = 0; j < KNN; j++) {
        r[j] = __fdiv_rn(1.0f, __fadd_rn(dd[j], 1e-8f));
        sum = __fadd_rn(sum, r[j]);
    }
#pragma unroll
    for (int j = 0; j < KNN; j++) {
        g_id[q * KNN + j] = id[j];
        g_w[q * KNN + j]  = __fdiv_rn(r[j], sum);
    }
}

// ============================================================
// 3) SGEMM: C[m,o]=sum_c A[m,c]*W[o,wcol0+c](+bias)
// ============================================================
__global__ void __launch_bounds__(256) gemm_kernel(
        const float* __restrict__ A, int K,
        const float* __restrict__ W, int wcol0,
        const float* __restrict__ bias, int dst)
{
    __shared__ float As[16][132];
    __shared__ float Bs[16][132];
    float* C = dst ? g_P : g_Q;

    int tid = threadIdx.x;
    int m0 = blockIdx.x * 128;
    int tx = tid & 15;
    int ty = tid >> 4;
    int lr = tid >> 2;
    int lc = (tid & 3) << 2;

    float acc[8][8];
#pragma unroll
    for (int i = 0; i < 8; i++)
#pragma unroll
        for (int j = 0; j < 8; j++) acc[i][j] = 0.f;

    for (int kt = 0; kt < K; kt += 16) {
        float4 a0 = *(const float4*)(A + (size_t)(m0 + lr) * K + kt + lc);
        float4 a1 = *(const float4*)(A + (size_t)(m0 + lr + 64) * K + kt + lc);
        float4 b0 = *(const float4*)(W + (size_t)lr * 384 + wcol0 + kt + lc);
        float4 b1 = *(const float4*)(W + (size_t)(lr + 64) * 384 + wcol0 + kt + lc);
        __syncthreads();
        As[lc + 0][lr] = a0.x; As[lc + 1][lr] = a0.y; As[lc + 2][lr] = a0.z; As[lc + 3][lr] = a0.w;
        As[lc + 0][lr + 64] = a1.x; As[lc + 1][lr + 64] = a1.y; As[lc + 2][lr + 64] = a1.z; As[lc + 3][lr + 64] = a1.w;
        Bs[lc + 0][lr] = b0.x; Bs[lc + 1][lr] = b0.y; Bs[lc + 2][lr] = b0.z; Bs[lc + 3][lr] = b0.w;
        Bs[lc + 0][lr + 64] = b1.x; Bs[lc + 1][lr + 64] = b1.y; Bs[lc + 2][lr + 64] = b1.z; Bs[lc + 3][lr + 64] = b1.w;
        __syncthreads();
#pragma unroll
        for (int kk = 0; kk < 16; kk++) {
            float4 af0 = *(float4*)&As[kk][ty * 4];
            float4 af1 = *(float4*)&As[kk][ty * 4 + 64];
            float4 bf0 = *(float4*)&Bs[kk][tx * 4];
            float4 bf1 = *(float4*)&Bs[kk][tx * 4 + 64];
            float av[8] = {af0.x, af0.y, af0.z, af0.w, af1.x, af1.y, af1.z, af1.w};
            float bv[8] = {bf0.x, bf0.y, bf0.z, bf0.w, bf1.x, bf1.y, bf1.z, bf1.w};
#pragma unroll
            for (int i = 0; i < 8; i++)
#pragma unroll
                for (int j = 0; j < 8; j++)
                    acc[i][j] = fmaf(av[i], bv[j], acc[i][j]);
        }
    }

    float bb[8] = {0.f, 0.f, 0.f, 0.f, 0.f, 0.f, 0.f, 0.f};
    if (bias) {
        float4 x0 = *(const float4*)(bias + tx * 4);
        float4 x1 = *(const float4*)(bias + tx * 4 + 64);
        bb[0] = x0.x; bb[1] = x0.y; bb[2] = x0.z; bb[3] = x0.w;
        bb[4] = x1.x; bb[5] = x1.y; bb[6] = x1.z; bb[7] = x1.w;
    }
#pragma unroll
    for (int i = 0; i < 8; i++) {
        int row = m0 + ty * 4 + (i < 4 ? i : 64 + i - 4);
        float4 v0 = make_float4(acc[i][0] + bb[0], acc[i][1] + bb[1],
                                acc[i][2] + bb[2], acc[i][3] + bb[3]);
        float4 v1 = make_float4(acc[i][4] + bb[4], acc[i][5] + bb[5],
                                acc[i][6] + bb[6], acc[i][7] + bb[7]);
        *(float4*)(C + (size_t)row * DOUT + tx * 4) = v0;
        *(float4*)(C + (size_t)row * DOUT + tx * 4 + 64) = v1;
    }
}

// ============================================================
// 4) combine (float4): warp per query, 4 queries per block
// ============================================================
__global__ void __launch_bounds__(128) combine_kernel(float* __restrict__ out) {
    int w = threadIdx.x >> 5, lane = threadIdx.x & 31;
    int q = blockIdx.x * 4 + w;
    __shared__ float sw[4][KNN];
    __shared__ int   sid[4][KNN];
    if (threadIdx.x < 64) {
        int wq = threadIdx.x >> 4, j = threadIdx.x & 15;
        sw[wq][j]  = g_w[(blockIdx.x * 4 + wq) * KNN + j];
        sid[wq][j] = g_id[(blockIdx.x * 4 + wq) * KNN + j];
    }
    __syncthreads();
    int base = q & ~(NPTS - 1);
    float4 acc = ((const float4*)(g_Q + (size_t)q * DOUT))[lane];
#pragma unroll
    for (int j = 0; j < KNN; j++) {
        float4 p = ((const float4*)(g_P + (size_t)(base + sid[w][j]) * DOUT))[lane];
        float wg = sw[w][j];
        acc.x = fmaf(wg, p.x, acc.x);
        acc.y = fmaf(wg, p.y, acc.y);
        acc.z = fmaf(wg, p.z, acc.z);
        acc.w = fmaf(wg, p.w, acc.w);
    }
    ((float4*)(out + (size_t)q * DOUT))[lane] = acc;
}

// ============================================================
// launcher: fork-join; both GEMMs on concurrent side streams
// ============================================================
static cudaStream_t s_g1 = nullptr, s_g2 = nullptr;
static cudaEvent_t  s_evFork = nullptr, s_evJ1 = nullptr, s_evJ2 = nullptr;

extern "C" void kernel_launch(void* const* d_in, const int* in_sizes, int n_in,
                              void* d_out, int out_size) {
    const float* xyz1    = (const float*)d_in[0];
    const float* xyz2    = (const float*)d_in[1];
    const float* points1 = (const float*)d_in[2];
    const float* points2 = (const float*)d_in[3];
    const float* W       = (const float*)d_in[4];
    const float* bias    = (const float*)d_in[5];
    (void)in_sizes; (void)n_in; (void)out_size;

    if (s_g1 == nullptr) {
        cudaStreamCreateWithFlags(&s_g1, cudaStreamNonBlocking);
        cudaStreamCreateWithFlags(&s_g2, cudaStreamNonBlocking);
        cudaEventCreateWithFlags(&s_evFork, cudaEventDisableTiming);
        cudaEventCreateWithFlags(&s_evJ1, cudaEventDisableTiming);
        cudaEventCreateWithFlags(&s_evJ2, cudaEventDisableTiming);
        cudaFuncSetAttribute(scan_kernel,
                             cudaFuncAttributeMaxDynamicSharedMemorySize, 65536);
    }

    cudaEventRecord(s_evFork, 0);
    cudaStreamWaitEvent(s_g1, s_evFork, 0);
    cudaStreamWaitEvent(s_g2, s_evFork, 0);

    // concurrent GEMMs (independent of kNN pipeline)
    gemm_kernel<<<NTOT / 128, 256, 0, s_g1>>>(points1, 128, W, 0,   bias,    0); // g_Q
    gemm_kernel<<<NTOT / 128, 256, 0, s_g2>>>(points2, 256, W, 128, nullptr, 1); // g_P
    cudaEventRecord(s_evJ1, s_g1);
    cudaEventRecord(s_evJ2, s_g2);

    // main stream: kNN pipeline
    pack_kernel<<<(NTOT / 2 + 255) / 256, 256>>>(xyz1);
    sample_kernel<<<NTOT / 256, 256>>>(xyz2);
    scan_kernel<<<256, 512, 65536>>>(xyz2);
    final_kernel<<<NTOT / 256, 256>>>();

    cudaStreamWaitEvent(0, s_evJ1, 0);
    cudaStreamWaitEvent(0, s_evJ2, 0);
    combine_kernel<<<NTOT / 4, 128>>>((float*)d_out);
}

// round 10
// speedup vs baseline: 1.4553x; 1.4553x over previous
#include <cuda_runtime.h>

#define NTOT 16384   // B*N
#define NPTS 8192    // N per batch
#define KNN  16
#define DOUT 128
#define STKN 12
#define TOPK_SMEM (65536 + 49152)   // keys 64KB + stack 48KB = 112KB

// ---- scratch (__device__ globals: allocation-free) ----
__device__ float4 g_keysA[NTOT / 2];     // (x0,x1,y0,y1) per key pair
__device__ float4 g_keysB[NTOT / 2];     // (z0,z1,n0,n1) per key pair
__device__ float  g_Q[NTOT * DOUT];
__device__ float  g_P[NTOT * DOUT];
__device__ float  g_md[2 * KNN * NTOT];  // half-merged dists, [j][half][q]
__device__ int    g_mi[2 * KNN * NTOT];  // half-merged ids
__device__ int    g_id[NTOT * KNN];
__device__ float  g_w[NTOT * KNN];

// ---- f32x2 packed helpers (two independent IEEE-rn fp32 ops) ----
__device__ __forceinline__ unsigned long long pk2(float lo, float hi) {
    unsigned long long v;
    asm("mov.b64 %0, {%1, %2};" : "=l"(v) : "f"(lo), "f"(hi));
    return v;
}
__device__ __forceinline__ void unpk2(float& lo, float& hi, unsigned long long v) {
    asm("mov.b64 {%0, %1}, %2;" : "=f"(lo), "=f"(hi) : "l"(v));
}
__device__ __forceinline__ unsigned long long mul2(unsigned long long a, unsigned long long b) {
    unsigned long long d;
    asm("mul.rn.f32x2 %0, %1, %2;" : "=l"(d) : "l"(a), "l"(b));
    return d;
}
__device__ __forceinline__ unsigned long long add2(unsigned long long a, unsigned long long b) {
    unsigned long long d;
    asm("add.rn.f32x2 %0, %1, %2;" : "=l"(d) : "l"(a), "l"(b));
    return d;
}
__device__ __forceinline__ unsigned long long fma2_(unsigned long long a, unsigned long long b,
                                                    unsigned long long c) {
    unsigned long long d;
    asm("fma.rn.f32x2 %0, %1, %2, %3;" : "=l"(d) : "l"(a), "l"(b), "l"(c));
    return d;
}

// packed distance for one key pair: d2 = (qn+kn) - 2*dot, reference rounding
__device__ __forceinline__ void dist2(float4 A, float4 Bv,
                                      unsigned long long qx2, unsigned long long qy2,
                                      unsigned long long qz2, unsigned long long qn2,
                                      unsigned long long m22, float& s0, float& s1) {
    unsigned long long kx2 = *(const unsigned long long*)&A.x;
    unsigned long long ky2 = *(const unsigned long long*)&A.z;
    unsigned long long kz2 = *(const unsigned long long*)&Bv.x;
    unsigned long long kn2 = *(const unsigned long long*)&Bv.z;
    unsigned long long dt = add2(add2(mul2(qx2, kx2), mul2(qy2, ky2)), mul2(qz2, kz2));
    unsigned long long d2 = fma2_(dt, m22, add2(qn2, kn2));   // -2*dot exact
    unpk2(s0, s1, d2);
}

// carry-insert (d,id) into sorted ascending 16-list, strict <
__device__ __forceinline__ void ins16(float (&d)[KNN], int (&id)[KNN], float cv, int ci) {
#pragma unroll
    for (int t = 0; t < KNN; t++) {
        bool p = cv < d[t];
        float od = d[t]; int oi = id[t];
        d[t]  = p ? cv : od;
        id[t] = p ? ci : oi;
        cv    = p ? od : cv;
        ci    = p ? oi : ci;
    }
}

// values-only carry (2 ops/slot)
__device__ __forceinline__ void insv16(float (&d)[KNN], float cv) {
#pragma unroll
    for (int t = 0; t < KNN; t++) {
        float lo = fminf(cv, d[t]);
        cv = fmaxf(cv, d[t]);
        d[t] = lo;
    }
}

// ============================================================
// 1) pack keys in pairs: A=(x0,x1,y0,y1), B=(z0,z1,n0,n1)
// ============================================================
__global__ void pack_kernel(const float* __restrict__ xyz1) {
    int p = blockIdx.x * 256 + threadIdx.x;
    if (p >= NTOT / 2) return;
    int k0 = 2 * p;
    float x0 = xyz1[3 * k0 + 0], y0 = xyz1[3 * k0 + 1], z0 = xyz1[3 * k0 + 2];
    float x1 = xyz1[3 * k0 + 3], y1 = xyz1[3 * k0 + 4], z1 = xyz1[3 * k0 + 5];
    float n0 = __fadd_rn(__fadd_rn(__fmul_rn(x0, x0), __fmul_rn(y0, y0)), __fmul_rn(z0, z0));
    float n1 = __fadd_rn(__fadd_rn(__fmul_rn(x1, x1), __fmul_rn(y1, y1)), __fmul_rn(z1, z1));
    g_keysA[p] = make_float4(x0, x1, y0, y1);
    g_keysB[p] = make_float4(z0, z1, n0, n1);
}

// ============================================================
// 2) top-16 NN, two-phase: 256 blocks x 512 threads, 2/SM.
//    Block (qg, half): 128 queries x 4096 keys, 4-way in-block
//    split -> 1024 keys/lane.
//    Phase A: values-only top-16 (cheap fmin/fmax flush) -> Tl.
//    Phase B: rescan, collect (d,id) with d <= Tl (~16+ties),
//    one ins16 pass. In-block 4-list merge in reused smem;
//    half-list written [j][half][q] for coalesced merge2.
// ============================================================
__global__ void __launch_bounds__(512, 2) topk_kernel(const float* __restrict__ xyz2) {
    extern __shared__ char smraw[];
    float4* skA  = (float4*)smraw;               // 2048 pairs, 32KB
    float4* skB  = (float4*)(smraw + 32768);     // 32KB
    float*  stk1 = (float*)(smraw + 65536);      // phase A: [12][512] 24KB
    float2* stk2 = (float2*)(smraw + 65536);     // phase B: [12][512] 48KB
    float*  sd   = (float*)smraw;                // after loops: 32KB
    int*    si   = (int*)(smraw + 32768);        // 32KB

    int tid  = threadIdx.x;
    int ql   = tid & 127;
    int h    = tid >> 7;
    int qg   = blockIdx.x >> 1;
    int half = blockIdx.x & 1;
    int q    = qg * 128 + ql;
    int b    = q >> 13;

    const float4* gA = g_keysA + b * 4096 + half * 2048;
    const float4* gB = g_keysB + b * 4096 + half * 2048;
    for (int i = tid; i < 2048; i += 512) { skA[i] = gA[i]; skB[i] = gB[i]; }
    __syncthreads();

    float qx = xyz2[3 * q + 0], qy = xyz2[3 * q + 1], qz = xyz2[3 * q + 2];
    float qn = __fadd_rn(__fadd_rn(__fmul_rn(qx, qx), __fmul_rn(qy, qy)), __fmul_rn(qz, qz));
    unsigned long long qx2 = pk2(qx, qx), qy2 = pk2(qy, qy), qz2 = pk2(qz, qz);
    unsigned long long qn2 = pk2(qn, qn), m22 = pk2(-2.0f, -2.0f);
    const float FINF = __int_as_float(0x7f800000);

    int pb = h * 512;     // lane's pair range in smem: [pb, pb+512)

    // ---------------- phase A: values only ----------------
    float d[KNN];
#pragma unroll
    for (int j = 0; j < KNN; j++) d[j] = 3.0e38f;
    int cnt = 0;

    for (int pp = 0; pp < 512; pp += 2) {
        if (__any_sync(0xffffffffu, cnt >= 6)) {
            for (int j = 0; j < STKN; j++) {
                if (!__any_sync(0xffffffffu, j < cnt)) break;
                float cv = (j < cnt) ? stk1[j * 512 + tid] : FINF;
                insv16(d, cv);
            }
            cnt = 0;
        }
#pragma unroll
        for (int u = 0; u < 2; u++) {
            float s0, s1;
            dist2(skA[pb + pp + u], skB[pb + pp + u], qx2, qy2, qz2, qn2, m22, s0, s1);
            if (s0 < d[KNN - 1]) { stk1[min(cnt, STKN - 1) * 512 + tid] = s0; cnt++; }
            if (s1 < d[KNN - 1]) { stk1[min(cnt, STKN - 1) * 512 + tid] = s1; cnt++; }
        }
    }
    for (int j = 0; j < STKN; j++) {
        if (!__any_sync(0xffffffffu, j < cnt)) break;
        float cv = (j < cnt) ? stk1[j * 512 + tid] : FINF;
        insv16(d, cv);
    }
    float Tl = d[KNN - 1];          // exact 16th smallest of this lane's keys
    __syncthreads();                // stk1 region becomes stk2 (float2)

    // ---------------- phase B: collect ids ----------------
    float dd[KNN]; int id[KNN];
#pragma unroll
    for (int j = 0; j < KNN; j++) { dd[j] = 3.0e38f; id[j] = 0; }
    cnt = 0;
    int kb = half * 4096 + h * 1024;   // batch-local key id base

    for (int pp = 0; pp < 512; pp += 2) {
        if (__any_sync(0xffffffffu, cnt >= 6)) {
            for (int j = 0; j < STKN; j++) {
                if (!__any_sync(0xffffffffu, j < cnt)) break;
                float2 e = stk2[j * 512 + tid];
                float cv = (j < cnt) ? e.x : FINF;
                ins16(dd, id, cv, __float_as_int(e.y));
            }
            cnt = 0;
        }
#pragma unroll
        for (int u = 0; u < 2; u++) {
            float s0, s1;
            dist2(skA[pb + pp + u], skB[pb + pp + u], qx2, qy2, qz2, qn2, m22, s0, s1);
            int k = kb + 2 * (pp + u);
            if (s0 <= Tl) { stk2[min(cnt, STKN - 1) * 512 + tid] = make_float2(s0, __int_as_float(k)); cnt++; }
            if (s1 <= Tl) { stk2[min(cnt, STKN - 1) * 512 + tid] = make_float2(s1, __int_as_float(k + 1)); cnt++; }
        }
    }
    for (int j = 0; j < STKN; j++) {
        if (!__any_sync(0xffffffffu, j < cnt)) break;
        float2 e = stk2[j * 512 + tid];
        float cv = (j < cnt) ? e.x : FINF;
        ins16(dd, id, cv, __float_as_int(e.y));
    }
    __syncthreads();                // key region dead; becomes sd/si

    // publish lane lists
    int base = (h * 128 + ql) * KNN;
#pragma unroll
    for (int j = 0; j < KNN; j++) { sd[base + j] = dd[j]; si[base + j] = id[j]; }
    __syncthreads();

    // stage 1: h=0 merges lists 0,1 -> slot 0; h=1 merges 2,3 -> slot 2
    if (h < 2) {
        int la = ((2 * h + 0) * 128 + ql) * KNN;
        int lb = ((2 * h + 1) * 128 + ql) * KNN;
        float rd[KNN]; int rid[KNN];
        int pa = la, pbm = lb;
#pragma unroll
        for (int j = 0; j < KNN; j++) {
            float va = sd[pa], vb = sd[pbm];
            int   xa = si[pa], xb = si[pbm];
            bool ta = (va < vb) || (va == vb && xa < xb);
            rd[j]  = ta ? va : vb;
            rid[j] = ta ? xa : xb;
            pa  += ta ? 1 : 0;
            pbm += ta ? 0 : 1;
        }
        int bo = ((2 * h) * 128 + ql) * KNN;
#pragma unroll
        for (int j = 0; j < KNN; j++) { sd[bo + j] = rd[j]; si[bo + j] = rid[j]; }
    }
    __syncthreads();

    // stage 2: h=0 merges slots 0,2 -> half-top16, write [j][half][q]
    if (h == 0) {
        int la = (0 * 128 + ql) * KNN;
        int lb = (2 * 128 + ql) * KNN;
        float rd[KNN]; int rid[KNN];
        int pa = la, pbm = lb;
#pragma unroll
        for (int j = 0; j < KNN; j++) {
            float va = sd[pa], vb = sd[pbm];
            int   xa = si[pa], xb = si[pbm];
            bool ta = (va < vb) || (va == vb && xa < xb);
            rd[j]  = ta ? va : vb;
            rid[j] = ta ? xa : xb;
            pa  += ta ? 1 : 0;
            pbm += ta ? 0 : 1;
        }
#pragma unroll
        for (int j = 0; j < KNN; j++) {
            g_md[(j * 2 + half) * NTOT + q] = rd[j];
            g_mi[(j * 2 + half) * NTOT + q] = rid[j];
        }
    }
}

// ============================================================
// 2b) merge2: per query, merge the two half-lists (coalesced
//     [j][half][q] loads), compute inverse-distance weights.
// ============================================================
__global__ void __launch_bounds__(256) merge2_kernel() {
    int q = blockIdx.x * 256 + threadIdx.x;
    int pa = 0, pb = 0;
    float va = g_md[0 * NTOT + q], vb = g_md[1 * NTOT + q];
    int   xa = g_mi[0 * NTOT + q], xb = g_mi[1 * NTOT + q];
    float rd[KNN]; int rid[KNN];
#pragma unroll
    for (int j = 0; j < KNN; j++) {
        bool ta = (va < vb) || (va == vb && xa < xb);
        rd[j]  = ta ? va : vb;
        rid[j] = ta ? xa : xb;
        if (ta) {
            pa++;
            if (pa < KNN) { va = g_md[(pa * 2) * NTOT + q]; xa = g_mi[(pa * 2) * NTOT + q]; }
            else          { va = 3.9e38f; xa = 0x7fffffff; }
        } else {
            pb++;
            if (pb < KNN) { vb = g_md[(pb * 2 + 1) * NTOT + q]; xb = g_mi[(pb * 2 + 1) * NTOT + q]; }
            else          { vb = 3.9e38f; xb = 0x7fffffff; }
        }
    }
    float r[KNN]; float sum = 0.f;
#pragma unroll
    for (int j = 0; j < KNN; j++) {
        r[j] = __fdiv_rn(1.0f, __fadd_rn(rd[j], 1e-8f));
        sum = __fadd_rn(sum, r[j]);
    }
#pragma unroll
    for (int j = 0; j < KNN; j++) {
        g_id[q * KNN + j] = rid[j];
        g_w[q * KNN + j]  = __fdiv_rn(r[j], sum);
    }
}

// ============================================================
// 3) SGEMM: C[m,o]=sum_c A[m,c]*W[o,wcol0+c](+bias)
// ============================================================
__global__ void __launch_bounds__(256) gemm_kernel(
        const float* __restrict__ A, int K,
        const float* __restrict__ W, int wcol0,
        const float* __restrict__ bias, int dst)
{
    __shared__ float As[16][132];
    __shared__ float Bs[16][132];
    float* C = dst ? g_P : g_Q;

    int tid = threadIdx.x;
    int m0 = blockIdx.x * 128;
    int tx = tid & 15;
    int ty = tid >> 4;
    int lr = tid >> 2;
    int lc = (tid & 3) << 2;

    float acc[8][8];
#pragma unroll
    for (int i = 0; i < 8; i++)
#pragma unroll
        for (int j = 0; j < 8; j++) acc[i][j] = 0.f;

    for (int kt = 0; kt < K; kt += 16) {
        float4 a0 = *(const float4*)(A + (size_t)(m0 + lr) * K + kt + lc);
        float4 a1 = *(const float4*)(A + (size_t)(m0 + lr + 64) * K + kt + lc);
        float4 b0 = *(const float4*)(W + (size_t)lr * 384 + wcol0 + kt + lc);
        float4 b1 = *(const float4*)(W + (size_t)(lr + 64) * 384 + wcol0 + kt + lc);
        __syncthreads();
        As[lc + 0][lr] = a0.x; As[lc + 1][lr] = a0.y; As[lc + 2][lr] = a0.z; As[lc + 3][lr] = a0.w;
        As[lc + 0][lr + 64] = a1.x; As[lc + 1][lr + 64] = a1.y; As[lc + 2][lr + 64] = a1.z; As[lc + 3][lr + 64] = a1.w;
        Bs[lc + 0][lr] = b0.x; Bs[lc + 1][lr] = b0.y; Bs[lc + 2][lr] = b0.z; Bs[lc + 3][lr] = b0.w;
        Bs[lc + 0][lr + 64] = b1.x; Bs[lc + 1][lr + 64] = b1.y; Bs[lc + 2][lr + 64] = b1.z; Bs[lc + 3][lr + 64] = b1.w;
        __syncthreads();
#pragma unroll
        for (int kk = 0; kk < 16; kk++) {
            float4 af0 = *(float4*)&As[kk][ty * 4];
            float4 af1 = *(float4*)&As[kk][ty * 4 + 64];
            float4 bf0 = *(float4*)&Bs[kk][tx * 4];
            float4 bf1 = *(float4*)&Bs[kk][tx * 4 + 64];
            float av[8] = {af0.x, af0.y, af0.z, af0.w, af1.x, af1.y, af1.z, af1.w};
            float bv[8] = {bf0.x, bf0.y, bf0.z, bf0.w, bf1.x, bf1.y, bf1.z, bf1.w};
#pragma unroll
            for (int i = 0; i < 8; i++)
#pragma unroll
                for (int j = 0; j < 8; j++)
                    acc[i][j] = fmaf(av[i], bv[j], acc[i][j]);
        }
    }

    float bb[8] = {0.f, 0.f, 0.f, 0.f, 0.f, 0.f, 0.f, 0.f};
    if (bias) {
        float4 x0 = *(const float4*)(bias + tx * 4);
        float4 x1 = *(const float4*)(bias + tx * 4 + 64);
        bb[0] = x0.x; bb[1] = x0.y; bb[2] = x0.z; bb[3] = x0.w;
        bb[4] = x1.x; bb[5] = x1.y; bb[6] = x1.z; bb[7] = x1.w;
    }
#pragma unroll
    for (int i = 0; i < 8; i++) {
        int row = m0 + ty * 4 + (i < 4 ? i : 64 + i - 4);
        float4 v0 = make_float4(acc[i][0] + bb[0], acc[i][1] + bb[1],
                                acc[i][2] + bb[2], acc[i][3] + bb[3]);
        float4 v1 = make_float4(acc[i][4] + bb[4], acc[i][5] + bb[5],
                                acc[i][6] + bb[6], acc[i][7] + bb[7]);
        *(float4*)(C + (size_t)row * DOUT + tx * 4) = v0;
        *(float4*)(C + (size_t)row * DOUT + tx * 4 + 64) = v1;
    }
}

// ============================================================
// 4) combine (float4): warp per query, 4 queries per block
// ============================================================
__global__ void __launch_bounds__(128) combine_kernel(float* __restrict__ out) {
    int w = threadIdx.x >> 5, lane = threadIdx.x & 31;
    int q = blockIdx.x * 4 + w;
    __shared__ float sw[4][KNN];
    __shared__ int   sid[4][KNN];
    if (threadIdx.x < 64) {
        int wq = threadIdx.x >> 4, j = threadIdx.x & 15;
        sw[wq][j]  = g_w[(blockIdx.x * 4 + wq) * KNN + j];
        sid[wq][j] = g_id[(blockIdx.x * 4 + wq) * KNN + j];
    }
    __syncthreads();
    int base = q & ~(NPTS - 1);
    float4 acc = ((const float4*)(g_Q + (size_t)q * DOUT))[lane];
#pragma unroll
    for (int j = 0; j < KNN; j++) {
        float4 p = ((const float4*)(g_P + (size_t)(base + sid[w][j]) * DOUT))[lane];
        float wg = sw[w][j];
        acc.x = fmaf(wg, p.x, acc.x);
        acc.y = fmaf(wg, p.y, acc.y);
        acc.z = fmaf(wg, p.z, acc.z);
        acc.w = fmaf(wg, p.w, acc.w);
    }
    ((float4*)(out + (size_t)q * DOUT))[lane] = acc;
}

// ============================================================
// launcher: fork-join; both GEMMs on concurrent side streams
// ============================================================
static cudaStream_t s_g1 = nullptr, s_g2 = nullptr;
static cudaEvent_t  s_evFork = nullptr, s_evJ1 = nullptr, s_evJ2 = nullptr;

extern "C" void kernel_launch(void* const* d_in, const int* in_sizes, int n_in,
                              void* d_out, int out_size) {
    const float* xyz1    = (const float*)d_in[0];
    const float* xyz2    = (const float*)d_in[1];
    const float* points1 = (const float*)d_in[2];
    const float* points2 = (const float*)d_in[3];
    const float* W       = (const float*)d_in[4];
    const float* bias    = (const float*)d_in[5];
    (void)in_sizes; (void)n_in; (void)out_size;

    if (s_g1 == nullptr) {
        cudaStreamCreateWithFlags(&s_g1, cudaStreamNonBlocking);
        cudaStreamCreateWithFlags(&s_g2, cudaStreamNonBlocking);
        cudaEventCreateWithFlags(&s_evFork, cudaEventDisableTiming);
        cudaEventCreateWithFlags(&s_evJ1, cudaEventDisableTiming);
        cudaEventCreateWithFlags(&s_evJ2, cudaEventDisableTiming);
        cudaFuncSetAttribute(topk_kernel,
                             cudaFuncAttributeMaxDynamicSharedMemorySize, TOPK_SMEM);
    }

    cudaEventRecord(s_evFork, 0);
    cudaStreamWaitEvent(s_g1, s_evFork, 0);
    cudaStreamWaitEvent(s_g2, s_evFork, 0);

    // concurrent GEMMs (independent of kNN pipeline)
    gemm_kernel<<<NTOT / 128, 256, 0, s_g1>>>(points1, 128, W, 0,   bias,    0); // g_Q
    gemm_kernel<<<NTOT / 128, 256, 0, s_g2>>>(points2, 256, W, 128, nullptr, 1); // g_P
    cudaEventRecord(s_evJ1, s_g1);
    cudaEventRecord(s_evJ2, s_g2);

    // main stream: kNN pipeline
    pack_kernel<<<(NTOT / 2 + 255) / 256, 256>>>(xyz1);
    topk_kernel<<<256, 512, TOPK_SMEM>>>(xyz2);
    merge2_kernel<<<NTOT / 256, 256>>>();

    cudaStreamWaitEvent(0, s_evJ1, 0);
    cudaStreamWaitEvent(0, s_evJ2, 0);
    combine_kernel<<<NTOT / 4, 128>>>((float*)d_out);
}

// round 11
// speedup vs baseline: 1.6754x; 1.1512x over previous
#include <cuda_runtime.h>

#define NTOT 16384   // B*N
#define NPTS 8192    // N per batch
#define KNN  16
#define DOUT 128
#define NLISTS 8     // partial lists per query (2 block-halves x 4 in-block)
#define STKN 12      // per-lane candidate stack depth
#define FLUSH_AT 8   // flush when cnt >= 8
#define TOPK_SMEM (32768 + 32768 + 49152)   // skA + skB + stack = 112KB

// ---- scratch (__device__ globals: allocation-free) ----
__device__ float4 g_keysA[NTOT / 2];     // (x0,x1,y0,y1) per key pair
__device__ float4 g_keysB[NTOT / 2];     // (z0,z1,n0,n1) per key pair
__device__ float  g_Q[NTOT * DOUT];
__device__ float  g_P[NTOT * DOUT];
// partial lists, layout [j*NLISTS + l][q] for coalesced merge; +1 row pad
__device__ float  g_pd[(KNN + 1) * NLISTS * NTOT];
__device__ int    g_pi[(KNN + 1) * NLISTS * NTOT];
__device__ int    g_id[NTOT * KNN];
__device__ float  g_w[NTOT * KNN];

// ---- f32x2 packed helpers (two independent IEEE-rn fp32 ops) ----
__device__ __forceinline__ unsigned long long pk2(float lo, float hi) {
    unsigned long long v;
    asm("mov.b64 %0, {%1, %2};" : "=l"(v) : "f"(lo), "f"(hi));
    return v;
}
__device__ __forceinline__ void unpk2(float& lo, float& hi, unsigned long long v) {
    asm("mov.b64 {%0, %1}, %2;" : "=f"(lo), "=f"(hi) : "l"(v));
}
__device__ __forceinline__ unsigned long long mul2(unsigned long long a, unsigned long long b) {
    unsigned long long d;
    asm("mul.rn.f32x2 %0, %1, %2;" : "=l"(d) : "l"(a), "l"(b));
    return d;
}
__device__ __forceinline__ unsigned long long add2(unsigned long long a, unsigned long long b) {
    unsigned long long d;
    asm("add.rn.f32x2 %0, %1, %2;" : "=l"(d) : "l"(a), "l"(b));
    return d;
}
__device__ __forceinline__ unsigned long long fma2_(unsigned long long a, unsigned long long b,
                                                    unsigned long long c) {
    unsigned long long d;
    asm("fma.rn.f32x2 %0, %1, %2, %3;" : "=l"(d) : "l"(a), "l"(b), "l"(c));
    return d;
}

// packed distance for one key pair: d2 = (qn+kn) - 2*dot, reference rounding
__device__ __forceinline__ void dist2(float4 A, float4 Bv,
                                      unsigned long long qx2, unsigned long long qy2,
                                      unsigned long long qz2, unsigned long long qn2,
                                      unsigned long long m22, float& s0, float& s1) {
    unsigned long long kx2 = *(const unsigned long long*)&A.x;
    unsigned long long ky2 = *(const unsigned long long*)&A.z;
    unsigned long long kz2 = *(const unsigned long long*)&Bv.x;
    unsigned long long kn2 = *(const unsigned long long*)&Bv.z;
    unsigned long long dt = add2(add2(mul2(qx2, kx2), mul2(qy2, ky2)), mul2(qz2, kz2));
    unsigned long long d2 = fma2_(dt, m22, add2(qn2, kn2));   // -2*dot exact
    unpk2(s0, s1, d2);
}

// carry-insert one (d,id) into sorted ascending 16-list, strict <
__device__ __forceinline__ void ins16(float (&d)[KNN], int (&id)[KNN], float cv, int ci) {
#pragma unroll
    for (int t = 0; t < KNN; t++) {
        bool p = cv < d[t];
        float od = d[t]; int oi = id[t];
        d[t]  = p ? cv : od;
        id[t] = p ? ci : oi;
        cv    = p ? od : cv;
        ci    = p ? oi : ci;
    }
}

// ============================================================
// 1) pack keys in pairs: A=(x0,x1,y0,y1), B=(z0,z1,n0,n1)
// ============================================================
__global__ void pack_kernel(const float* __restrict__ xyz1) {
    int p = blockIdx.x * 256 + threadIdx.x;
    if (p >= NTOT / 2) return;
    int k0 = 2 * p;
    float x0 = xyz1[3 * k0 + 0], y0 = xyz1[3 * k0 + 1], z0 = xyz1[3 * k0 + 2];
    float x1 = xyz1[3 * k0 + 3], y1 = xyz1[3 * k0 + 4], z1 = xyz1[3 * k0 + 5];
    float n0 = __fadd_rn(__fadd_rn(__fmul_rn(x0, x0), __fmul_rn(y0, y0)), __fmul_rn(z0, z0));
    float n1 = __fadd_rn(__fadd_rn(__fmul_rn(x1, x1), __fmul_rn(y1, y1)), __fmul_rn(z1, z1));
    g_keysA[p] = make_float4(x0, x1, y0, y1);
    g_keysB[p] = make_float4(z0, z1, n0, n1);
}

// ============================================================
// 2) top-16 NN (R7-measured loop): 256 blocks x 512 threads.
//    Block (qg, half): 128 queries, 4096 keys, 4-way in-block
//    split -> 1024 keys/lane. 12-deep smem stack, flush@8
//    checked every 2 pairs (max cnt 11 <= 12).
//    Sorted per-lane lists -> global in [j*NLISTS+l][q] layout
//    (coalesced for both writer and merge8 reader).
// ============================================================
__global__ void __launch_bounds__(512, 2) topk_kernel(const float* __restrict__ xyz2) {
    extern __shared__ char smraw[];
    float4* skA = (float4*)smraw;                // 2048 pairs, 32KB
    float4* skB = (float4*)(smraw + 32768);      // 32KB
    float2* stk = (float2*)(smraw + 65536);      // [12][512] 48KB

    int tid  = threadIdx.x;
    int ql   = tid & 127;
    int h    = tid >> 7;
    int qg   = blockIdx.x >> 1;
    int half = blockIdx.x & 1;
    int q    = qg * 128 + ql;
    int b    = q >> 13;

    const float4* gA = g_keysA + b * 4096 + half * 2048;
    const float4* gB = g_keysB + b * 4096 + half * 2048;
    for (int i = tid; i < 2048; i += 512) { skA[i] = gA[i]; skB[i] = gB[i]; }
    __syncthreads();

    float qx = xyz2[3 * q + 0], qy = xyz2[3 * q + 1], qz = xyz2[3 * q + 2];
    float qn = __fadd_rn(__fadd_rn(__fmul_rn(qx, qx), __fmul_rn(qy, qy)), __fmul_rn(qz, qz));
    unsigned long long qx2 = pk2(qx, qx), qy2 = pk2(qy, qy), qz2 = pk2(qz, qz);
    unsigned long long qn2 = pk2(qn, qn), m22 = pk2(-2.0f, -2.0f);
    const float FINF = __int_as_float(0x7f800000);

    float d[KNN];  int id[KNN];
#pragma unroll
    for (int j = 0; j < KNN; j++) { d[j] = 3.0e38f; id[j] = 0; }

    int cnt = 0;
    int pb = h * 512;
    int kb = half * 4096 + h * 1024;     // batch-local key id base

    for (int pp = 0; pp < 512; pp += 2) {
        if (__any_sync(0xffffffffu, cnt >= FLUSH_AT)) {
            for (int j = 0; j < STKN; j++) {
                if (!__any_sync(0xffffffffu, j < cnt)) break;
                float2 e = stk[j * 512 + tid];
                float cv = (j < cnt) ? e.x : FINF;
                ins16(d, id, cv, __float_as_int(e.y));
            }
            cnt = 0;
        }
#pragma unroll
        for (int u = 0; u < 2; u++) {
            float s0, s1;
            dist2(skA[pb + pp + u], skB[pb + pp + u], qx2, qy2, qz2, qn2, m22, s0, s1);
            int k = kb + 2 * (pp + u);
            if (s0 < d[KNN - 1]) { stk[min(cnt, STKN - 1) * 512 + tid] = make_float2(s0, __int_as_float(k)); cnt++; }
            if (s1 < d[KNN - 1]) { stk[min(cnt, STKN - 1) * 512 + tid] = make_float2(s1, __int_as_float(k + 1)); cnt++; }
        }
    }
    // final flush
    for (int j = 0; j < STKN; j++) {
        if (!__any_sync(0xffffffffu, j < cnt)) break;
        float2 e = stk[j * 512 + tid];
        float cv = (j < cnt) ? e.x : FINF;
        ins16(d, id, cv, __float_as_int(e.y));
    }

    // write sorted partial list, coalesced layout [j*NLISTS + l][q]
    int l = half * 4 + h;
#pragma unroll
    for (int j = 0; j < KNN; j++) {
        g_pd[(size_t)(j * NLISTS + l) * NTOT + q] = d[j];
        g_pi[(size_t)(j * NLISTS + l) * NTOT + q] = id[j];
    }
}

// ============================================================
// 2b) merge 8 sorted 16-lists per query (register heads,
//     coalesced loads), compute inverse-distance weights.
//     Exact top_k tie order: (d, id) lexicographic.
// ============================================================
__global__ void __launch_bounds__(256) merge8_kernel() {
    int q = blockIdx.x * 256 + threadIdx.x;
    float hv[NLISTS]; int hi[NLISTS]; int pos[NLISTS];
#pragma unroll
    for (int l = 0; l < NLISTS; l++) {
        hv[l] = g_pd[(size_t)l * NTOT + q];      // j=0 row
        hi[l] = g_pi[(size_t)l * NTOT + q];
        pos[l] = 0;
    }
    float rd[KNN];
#pragma unroll
    for (int j = 0; j < KNN; j++) {
        float bv = hv[0]; int bi = hi[0]; int bl = 0;
#pragma unroll
        for (int l = 1; l < NLISTS; l++) {
            bool t = (hv[l] < bv) || (hv[l] == bv && hi[l] < bi);
            bv = t ? hv[l] : bv;
            bi = t ? hi[l] : bi;
            bl = t ? l : bl;
        }
        rd[j] = bv;
        g_id[q * KNN + j] = bi;
#pragma unroll
        for (int l = 0; l < NLISTS; l++) {
            bool adv = (l == bl);
            int np = pos[l] + (adv ? 1 : 0);
            pos[l] = np;
            if (adv) {
                size_t o = (size_t)(np * NLISTS + l) * NTOT + q;   // pad row safe
                hv[l] = g_pd[o]; hi[l] = g_pi[o];
            }
        }
    }
    float r[KNN]; float sum = 0.f;
#pragma unroll
    for (int j = 0; j < KNN; j++) {
        r[j] = __fdiv_rn(1.0f, __fadd_rn(rd[j], 1e-8f));
        sum = __fadd_rn(sum, r[j]);
    }
#pragma unroll
    for (int j = 0; j < KNN; j++)
        g_w[q * KNN + j] = __fdiv_rn(r[j], sum);
}

// ============================================================
// 3) SGEMM: C[m,o]=sum_c A[m,c]*W[o,wcol0+c](+bias)
// ============================================================
__global__ void __launch_bounds__(256) gemm_kernel(
        const float* __restrict__ A, int K,
        const float* __restrict__ W, int wcol0,
        const float* __restrict__ bias, int dst)
{
    __shared__ float As[16][132];
    __shared__ float Bs[16][132];
    float* C = dst ? g_P : g_Q;

    int tid = threadIdx.x;
    int m0 = blockIdx.x * 128;
    int tx = tid & 15;
    int ty = tid >> 4;
    int lr = tid >> 2;
    int lc = (tid & 3) << 2;

    float acc[8][8];
#pragma unroll
    for (int i = 0; i < 8; i++)
#pragma unroll
        for (int j = 0; j < 8; j++) acc[i][j] = 0.f;

    for (int kt = 0; kt < K; kt += 16) {
        float4 a0 = *(const float4*)(A + (size_t)(m0 + lr) * K + kt + lc);
        float4 a1 = *(const float4*)(A + (size_t)(m0 + lr + 64) * K + kt + lc);
        float4 b0 = *(const float4*)(W + (size_t)lr * 384 + wcol0 + kt + lc);
        float4 b1 = *(const float4*)(W + (size_t)(lr + 64) * 384 + wcol0 + kt + lc);
        __syncthreads();
        As[lc + 0][lr] = a0.x; As[lc + 1][lr] = a0.y; As[lc + 2][lr] = a0.z; As[lc + 3][lr] = a0.w;
        As[lc + 0][lr + 64] = a1.x; As[lc + 1][lr + 64] = a1.y; As[lc + 2][lr + 64] = a1.z; As[lc + 3][lr + 64] = a1.w;
        Bs[lc + 0][lr] = b0.x; Bs[lc + 1][lr] = b0.y; Bs[lc + 2][lr] = b0.z; Bs[lc + 3][lr] = b0.w;
        Bs[lc + 0][lr + 64] = b1.x; Bs[lc + 1][lr + 64] = b1.y; Bs[lc + 2][lr + 64] = b1.z; Bs[lc + 3][lr + 64] = b1.w;
        __syncthreads();
#pragma unroll
        for (int kk = 0; kk < 16; kk++) {
            float4 af0 = *(float4*)&As[kk][ty * 4];
            float4 af1 = *(float4*)&As[kk][ty * 4 + 64];
            float4 bf0 = *(float4*)&Bs[kk][tx * 4];
            float4 bf1 = *(float4*)&Bs[kk][tx * 4 + 64];
            float av[8] = {af0.x, af0.y, af0.z, af0.w, af1.x, af1.y, af1.z, af1.w};
            float bv[8] = {bf0.x, bf0.y, bf0.z, bf0.w, bf1.x, bf1.y, bf1.z, bf1.w};
#pragma unroll
            for (int i = 0; i < 8; i++)
#pragma unroll
                for (int j = 0; j < 8; j++)
                    acc[i][j] = fmaf(av[i], bv[j], acc[i][j]);
        }
    }

    float bb[8] = {0.f, 0.f, 0.f, 0.f, 0.f, 0.f, 0.f, 0.f};
    if (bias) {
        float4 x0 = *(const float4*)(bias + tx * 4);
        float4 x1 = *(const float4*)(bias + tx * 4 + 64);
        bb[0] = x0.x; bb[1] = x0.y; bb[2] = x0.z; bb[3] = x0.w;
        bb[4] = x1.x; bb[5] = x1.y; bb[6] = x1.z; bb[7] = x1.w;
    }
#pragma unroll
    for (int i = 0; i < 8; i++) {
        int row = m0 + ty * 4 + (i < 4 ? i : 64 + i - 4);
        float4 v0 = make_float4(acc[i][0] + bb[0], acc[i][1] + bb[1],
                                acc[i][2] + bb[2], acc[i][3] + bb[3]);
        float4 v1 = make_float4(acc[i][4] + bb[4], acc[i][5] + bb[5],
                                acc[i][6] + bb[6], acc[i][7] + bb[7]);
        *(float4*)(C + (size_t)row * DOUT + tx * 4) = v0;
        *(float4*)(C + (size_t)row * DOUT + tx * 4 + 64) = v1;
    }
}

// ============================================================
// 4) combine (float4): warp per query, 4 queries per block
// ============================================================
__global__ void __launch_bounds__(128) combine_kernel(float* __restrict__ out) {
    int w = threadIdx.x >> 5, lane = threadIdx.x & 31;
    int q = blockIdx.x * 4 + w;
    __shared__ float sw[4][KNN];
    __shared__ int   sid[4][KNN];
    if (threadIdx.x < 64) {
        int wq = threadIdx.x >> 4, j = threadIdx.x & 15;
        sw[wq][j]  = g_w[(blockIdx.x * 4 + wq) * KNN + j];
        sid[wq][j] = g_id[(blockIdx.x * 4 + wq) * KNN + j];
    }
    __syncthreads();
    int base = q & ~(NPTS - 1);
    float4 acc = ((const float4*)(g_Q + (size_t)q * DOUT))[lane];
#pragma unroll
    for (int j = 0; j < KNN; j++) {
        float4 p = ((const float4*)(g_P + (size_t)(base + sid[w][j]) * DOUT))[lane];
        float wg = sw[w][j];
        acc.x = fmaf(wg, p.x, acc.x);
        acc.y = fmaf(wg, p.y, acc.y);
        acc.z = fmaf(wg, p.z, acc.z);
        acc.w = fmaf(wg, p.w, acc.w);
    }
    ((float4*)(out + (size_t)q * DOUT))[lane] = acc;
}

// ============================================================
// launcher: fork-join; both GEMMs on concurrent side streams
// ============================================================
static cudaStream_t s_g1 = nullptr, s_g2 = nullptr;
static cudaEvent_t  s_evFork = nullptr, s_evJ1 = nullptr, s_evJ2 = nullptr;

extern "C" void kernel_launch(void* const* d_in, const int* in_sizes, int n_in,
                              void* d_out, int out_size) {
    const float* xyz1    = (const float*)d_in[0];
    const float* xyz2    = (const float*)d_in[1];
    const float* points1 = (const float*)d_in[2];
    const float* points2 = (const float*)d_in[3];
    const float* W       = (const float*)d_in[4];
    const float* bias    = (const float*)d_in[5];
    (void)in_sizes; (void)n_in; (void)out_size;

    if (s_g1 == nullptr) {
        cudaStreamCreateWithFlags(&s_g1, cudaStreamNonBlocking);
        cudaStreamCreateWithFlags(&s_g2, cudaStreamNonBlocking);
        cudaEventCreateWithFlags(&s_evFork, cudaEventDisableTiming);
        cudaEventCreateWithFlags(&s_evJ1, cudaEventDisableTiming);
        cudaEventCreateWithFlags(&s_evJ2, cudaEventDisableTiming);
        cudaFuncSetAttribute(topk_kernel,
                             cudaFuncAttributeMaxDynamicSharedMemorySize, TOPK_SMEM);
    }

    cudaEventRecord(s_evFork, 0);
    cudaStreamWaitEvent(s_g1, s_evFork, 0);
    cudaStreamWaitEvent(s_g2, s_evFork, 0);

    // concurrent GEMMs (independent of kNN pipeline)
    gemm_kernel<<<NTOT / 128, 256, 0, s_g1>>>(points1, 128, W, 0,   bias,    0); // g_Q
    gemm_kernel<<<NTOT / 128, 256, 0, s_g2>>>(points2, 256, W, 128, nullptr, 1); // g_P
    cudaEventRecord(s_evJ1, s_g1);
    cudaEventRecord(s_evJ2, s_g2);

    // main stream: kNN pipeline
    pack_kernel<<<(NTOT / 2 + 255) / 256, 256>>>(xyz1);
    topk_kernel<<<256, 512, TOPK_SMEM>>>(xyz2);
    merge8_kernel<<<NTOT / 256, 256>>>();

    cudaStreamWaitEvent(0, s_evJ1, 0);
    cudaStreamWaitEvent(0, s_evJ2, 0);
    combine_kernel<<<NTOT / 4, 128>>>((float*)d_out);
}